// round 4
// baseline (speedup 1.0000x reference)
#include <cuda_runtime.h>
#include <math.h>
#include <stdint.h>

// ---------------- model constants ----------------
#define B_    2
#define N_    1024
#define D_    256
#define H_    8
#define DH_   32
#define K_    4
#define IN_   1024
#define V_    32000
#define CK_   3
#define MAXL_ 8
#define TRUNC_ 4
#define BN_   (B_ * N_)

// ---------------- scratch (device globals, no allocs) ----------------
__device__ float g_X  [BN_ * D_];
__device__ float g_Q  [BN_ * D_];
__device__ float g_Hc [BN_ * D_];
__device__ float g_pq [BN_ * D_];
__device__ float g_pk [BN_ * D_];
__device__ float g_v  [BN_ * D_];
__device__ float g_cmv[BN_ * D_];
__device__ float g_hn [BN_ * D_];
__device__ float g_gu [BN_ * 2 * IN_];
__device__ float g_hc2[BN_ * IN_];
__device__ float g_qn [BN_ * D_];

// ---------------- tf32 helpers ----------------
__device__ __forceinline__ void split2(float x, uint32_t& hi, uint32_t& lo) {
    uint32_t h;
    asm("cvt.rna.tf32.f32 %0, %1;" : "=r"(h) : "f"(x));
    float r = x - __uint_as_float(h);
    uint32_t l;
    asm("cvt.rna.tf32.f32 %0, %1;" : "=r"(l) : "f"(r));
    hi = h; lo = l;
}

__device__ __forceinline__ void mma8(float* c, const uint32_t* a, uint32_t b0, uint32_t b1) {
    asm volatile("mma.sync.aligned.m16n8k8.row.col.f32.tf32.tf32.f32 "
                 "{%0,%1,%2,%3}, {%4,%5,%6,%7}, {%8,%9}, {%0,%1,%2,%3};"
                 : "+f"(c[0]), "+f"(c[1]), "+f"(c[2]), "+f"(c[3])
                 : "r"(a[0]), "r"(a[1]), "r"(a[2]), "r"(a[3]), "r"(b0), "r"(b1));
}

// ---------------- misc helpers ----------------
__device__ __forceinline__ float blockReduceSum256(float v) {
    __shared__ float sh[8];
    int lane = threadIdx.x & 31;
    int wid  = threadIdx.x >> 5;
#pragma unroll
    for (int o = 16; o > 0; o >>= 1) v += __shfl_down_sync(0xffffffffu, v, o);
    __syncthreads();
    if (lane == 0) sh[wid] = v;
    __syncthreads();
    float t = 0.f;
#pragma unroll
    for (int i = 0; i < 8; i++) t += sh[i];
    return t;
}

// ---------------- embedding + positional ----------------
__global__ void embed_kernel(const int* __restrict__ ids,
                             const float* __restrict__ emb,
                             const float* __restrict__ pos,
                             float* __restrict__ X) {
    int row = blockIdx.x;
    int d   = threadIdx.x;
    int n   = row & (N_ - 1);
    int id  = ids[row];
    X[(size_t)row * D_ + d] = emb[(size_t)id * D_ + d] + pos[(size_t)n * D_ + d];
}

// ---------------- layernorm ----------------
__global__ void ln_kernel(const float* __restrict__ in,
                          const float* __restrict__ w,
                          const float* __restrict__ b,
                          const float* __restrict__ addX,
                          float* __restrict__ out,
                          float* __restrict__ out2) {
    int row = blockIdx.x;
    int d   = threadIdx.x;
    float x  = in[(size_t)row * D_ + d];
    float mu = blockReduceSum256(x) * (1.f / D_);
    float dx = x - mu;
    float var = blockReduceSum256(dx * dx) * (1.f / D_);
    float y = dx * rsqrtf(var + 1e-5f) * w[d] + b[d];
    if (addX) y += addX[(size_t)row * D_ + d];
    out[(size_t)row * D_ + d] = y;
    if (out2) out2[(size_t)row * D_ + d] = y;
}

// ---------------- tensor-core GEMM (tf32, NSPLIT=3 -> ~fp32, NSPLIT=1 -> fast) ----
// C[M,N] = epi(A[M,K] @ B[K,N]); epi: 0 none, 1 elu(x)+1, 2 aux+softplus(dts[kidx])*x, 3 aux+x
#define GBM 128
#define GBN 64
#define GBK 32
#define GEMM_SMEM_3 ((2 * (128 * 33) + 2 * (32 * 65)) * 4)
#define GEMM_SMEM_1 (((128 * 33) + (32 * 65)) * 4)

template <int NSPLIT>
__global__ void __launch_bounds__(256, 2)
gemm_tc(const float* __restrict__ A, const float* __restrict__ Bm, float* __restrict__ C,
        int M, int N, int Kd, int epi, const float* __restrict__ aux,
        const float* __restrict__ dts, int kidx)
{
    extern __shared__ uint32_t sh[];
    uint32_t* Ah = sh;                      // 128*33
    uint32_t* Bh = Ah + 128 * 33;           // 32*65
    uint32_t* Al = Bh + 32 * 65;            // 128*33 (NSPLIT==3 only)
    uint32_t* Bl = Al + 128 * 33;           // 32*65  (NSPLIT==3 only)

    const int tid  = threadIdx.x;
    const int lane = tid & 31;
    const int wid  = tid >> 5;
    const int g  = lane >> 2, tg = lane & 3;
    const int wm = wid & 3,   wn = wid >> 2;          // 4 (m) x 2 (n)
    const int row0 = blockIdx.y * GBM;
    const int col0 = blockIdx.x * GBN;

    float acc[2][4][4];
#pragma unroll
    for (int a = 0; a < 2; a++)
#pragma unroll
        for (int b = 0; b < 4; b++)
#pragma unroll
            for (int c = 0; c < 4; c++) acc[a][b][c] = 0.f;

    for (int kt = 0; kt < Kd; kt += GBK) {
        __syncthreads();
        // A tile 128x32
#pragma unroll
        for (int it = 0; it < 4; it++) {
            int flat = it * 256 + tid;
            int m  = flat >> 3;
            int kq = (flat & 7) << 2;
            float4 av = *(const float4*)(A + (size_t)(row0 + m) * Kd + kt + kq);
            float vv[4] = {av.x, av.y, av.z, av.w};
#pragma unroll
            for (int j = 0; j < 4; j++) {
                uint32_t hi, lo; split2(vv[j], hi, lo);
                Ah[m * 33 + kq + j] = hi;
                if (NSPLIT == 3) Al[m * 33 + kq + j] = lo;
            }
        }
        // B tile 32x64
#pragma unroll
        for (int it = 0; it < 2; it++) {
            int flat = it * 256 + tid;
            int kk = flat >> 4;
            int nq = (flat & 15) << 2;
            float4 bv = *(const float4*)(Bm + (size_t)(kt + kk) * N + col0 + nq);
            float vv[4] = {bv.x, bv.y, bv.z, bv.w};
#pragma unroll
            for (int j = 0; j < 4; j++) {
                uint32_t hi, lo; split2(vv[j], hi, lo);
                Bh[kk * 65 + nq + j] = hi;
                if (NSPLIT == 3) Bl[kk * 65 + nq + j] = lo;
            }
        }
        __syncthreads();

#pragma unroll
        for (int ks = 0; ks < 4; ks++) {
            int kb = ks * 8;
            uint32_t ah[2][4], al[2][4];
#pragma unroll
            for (int mt = 0; mt < 2; mt++) {
                int r = wm * 32 + mt * 16;
                ah[mt][0] = Ah[(r + g) * 33 + kb + tg];
                ah[mt][1] = Ah[(r + g + 8) * 33 + kb + tg];
                ah[mt][2] = Ah[(r + g) * 33 + kb + tg + 4];
                ah[mt][3] = Ah[(r + g + 8) * 33 + kb + tg + 4];
                if (NSPLIT == 3) {
                    al[mt][0] = Al[(r + g) * 33 + kb + tg];
                    al[mt][1] = Al[(r + g + 8) * 33 + kb + tg];
                    al[mt][2] = Al[(r + g) * 33 + kb + tg + 4];
                    al[mt][3] = Al[(r + g + 8) * 33 + kb + tg + 4];
                }
            }
#pragma unroll
            for (int nt = 0; nt < 4; nt++) {
                int c = wn * 32 + nt * 8;
                uint32_t bh0 = Bh[(kb + tg) * 65 + c + g];
                uint32_t bh1 = Bh[(kb + tg + 4) * 65 + c + g];
#pragma unroll
                for (int mt = 0; mt < 2; mt++) mma8(acc[mt][nt], ah[mt], bh0, bh1);
                if (NSPLIT == 3) {
                    uint32_t bl0 = Bl[(kb + tg) * 65 + c + g];
                    uint32_t bl1 = Bl[(kb + tg + 4) * 65 + c + g];
#pragma unroll
                    for (int mt = 0; mt < 2; mt++) {
                        mma8(acc[mt][nt], al[mt], bh0, bh1);
                        mma8(acc[mt][nt], ah[mt], bl0, bl1);
                    }
                }
            }
        }
    }

    float sp = (epi == 2) ? log1pf(expf(dts[kidx])) : 0.f;
#pragma unroll
    for (int mt = 0; mt < 2; mt++) {
#pragma unroll
        for (int nt = 0; nt < 4; nt++) {
            int r = row0 + wm * 32 + mt * 16 + g;
            int c = col0 + wn * 32 + nt * 8 + 2 * tg;
#pragma unroll
            for (int e = 0; e < 4; e++) {
                int rr = r + (e >> 1) * 8;
                int cc = c + (e & 1);
                size_t o = (size_t)rr * N + cc;
                float x = acc[mt][nt][e];
                float y;
                if (epi == 1)      y = (x > 0.f) ? (x + 1.f) : expf(x);
                else if (epi == 2) y = aux[o] + sp * x;
                else if (epi == 3) y = aux[o] + x;
                else               y = x;
                C[o] = y;
            }
        }
    }
}

// ---------------- tensor-core attention (tf32x3 flash-style) ----------------
// per (b,h): S = pq@pk^T (64q x 64k tiles), W = relu(S)^2, C = W@v accum,
// out = C/(rowsum+1) - v
#define ATT_SMEM ((6 * 64 * 33 + 64 * 68 + 256 + 64) * 4)

__global__ void __launch_bounds__(256)
attn_tc(const float* __restrict__ pq_, const float* __restrict__ pk_,
        const float* __restrict__ v_, float* __restrict__ cmv)
{
    extern __shared__ uint32_t sh[];
    uint32_t* qh = sh;
    uint32_t* ql = qh + 64 * 33;
    uint32_t* kh = ql + 64 * 33;
    uint32_t* kl = kh + 64 * 33;
    uint32_t* vh = kl + 64 * 33;
    uint32_t* vl = vh + 64 * 33;
    float* Ssm  = (float*)(vl + 64 * 33);    // 64 x 68
    float* ssum = Ssm + 64 * 68;             // 256
    float* sinv = ssum + 256;                // 64

    const int tid  = threadIdx.x;
    const int lane = tid & 31, wid = tid >> 5;
    const int g = lane >> 2, tg = lane & 3;
    const int wm = wid & 1, wn = wid >> 1;   // 2 (m) x 4 (n)
    const int bh = blockIdx.x;
    const int b = bh >> 3, h = bh & 7;
    const int qb = blockIdx.y;

    // load pq tile (64 x 32), split
#pragma unroll
    for (int it = 0; it < 2; it++) {
        int flat = it * 256 + tid;
        int r  = flat >> 3;
        int dq = (flat & 7) << 2;
        float4 av = *(const float4*)(pq_ + (size_t)(b * N_ + qb * 64 + r) * D_ + h * DH_ + dq);
        float vv[4] = {av.x, av.y, av.z, av.w};
#pragma unroll
        for (int j = 0; j < 4; j++) {
            uint32_t hi, lo; split2(vv[j], hi, lo);
            qh[r * 33 + dq + j] = hi;
            ql[r * 33 + dq + j] = lo;
        }
    }

    float cacc[2][4];
#pragma unroll
    for (int mt = 0; mt < 2; mt++)
#pragma unroll
        for (int e = 0; e < 4; e++) cacc[mt][e] = 0.f;
    float srow = 0.f;
    const int myrow = tid >> 2, myq = tid & 3;

    for (int kt = 0; kt < N_; kt += 64) {
        __syncthreads();
        // load pk / v tiles (64 x 32 each), split
#pragma unroll
        for (int it = 0; it < 2; it++) {
            int flat = it * 256 + tid;
            int r  = flat >> 3;
            int dq = (flat & 7) << 2;
            size_t go = (size_t)(b * N_ + kt + r) * D_ + h * DH_ + dq;
            float4 kv4 = *(const float4*)(pk_ + go);
            float4 vv4 = *(const float4*)(v_ + go);
            float kk[4] = {kv4.x, kv4.y, kv4.z, kv4.w};
            float vv[4] = {vv4.x, vv4.y, vv4.z, vv4.w};
#pragma unroll
            for (int j = 0; j < 4; j++) {
                uint32_t hi, lo;
                split2(kk[j], hi, lo); kh[r * 33 + dq + j] = hi; kl[r * 33 + dq + j] = lo;
                split2(vv[j], hi, lo); vh[r * 33 + dq + j] = hi; vl[r * 33 + dq + j] = lo;
            }
        }
        __syncthreads();

        // phase 1: S = pq @ pk^T, warp tile 32x16
        float sacc[2][2][4];
#pragma unroll
        for (int mt = 0; mt < 2; mt++)
#pragma unroll
            for (int nt = 0; nt < 2; nt++)
#pragma unroll
                for (int e = 0; e < 4; e++) sacc[mt][nt][e] = 0.f;

#pragma unroll
        for (int ks = 0; ks < 4; ks++) {
            int kb = ks * 8;
            uint32_t ah[2][4], al[2][4];
#pragma unroll
            for (int mt = 0; mt < 2; mt++) {
                int r = wm * 32 + mt * 16;
                ah[mt][0] = qh[(r + g) * 33 + kb + tg];
                ah[mt][1] = qh[(r + g + 8) * 33 + kb + tg];
                ah[mt][2] = qh[(r + g) * 33 + kb + tg + 4];
                ah[mt][3] = qh[(r + g + 8) * 33 + kb + tg + 4];
                al[mt][0] = ql[(r + g) * 33 + kb + tg];
                al[mt][1] = ql[(r + g + 8) * 33 + kb + tg];
                al[mt][2] = ql[(r + g) * 33 + kb + tg + 4];
                al[mt][3] = ql[(r + g + 8) * 33 + kb + tg + 4];
            }
#pragma unroll
            for (int nt = 0; nt < 2; nt++) {
                int c = wn * 16 + nt * 8;
                uint32_t bh0 = kh[(c + g) * 33 + kb + tg];
                uint32_t bh1 = kh[(c + g) * 33 + kb + tg + 4];
                uint32_t bl0 = kl[(c + g) * 33 + kb + tg];
                uint32_t bl1 = kl[(c + g) * 33 + kb + tg + 4];
#pragma unroll
                for (int mt = 0; mt < 2; mt++) {
                    mma8(sacc[mt][nt], ah[mt], bh0, bh1);
                    mma8(sacc[mt][nt], al[mt], bh0, bh1);
                    mma8(sacc[mt][nt], ah[mt], bl0, bl1);
                }
            }
        }
        // relu^2 -> Ssm
#pragma unroll
        for (int mt = 0; mt < 2; mt++)
#pragma unroll
            for (int nt = 0; nt < 2; nt++) {
                int r = wm * 32 + mt * 16 + g;
                int c = wn * 16 + nt * 8 + 2 * tg;
#pragma unroll
                for (int e = 0; e < 4; e++) {
                    int rr = r + (e >> 1) * 8, cc = c + (e & 1);
                    float w = fmaxf(sacc[mt][nt][e], 0.f);
                    Ssm[rr * 68 + cc] = w * w;
                }
            }
        __syncthreads();

        // rowsum partial (each thread: one row quarter)
        {
            const float* spp = Ssm + myrow * 68 + myq * 16;
            float t = 0.f;
#pragma unroll
            for (int j = 0; j < 16; j++) t += spp[j];
            srow += t;
        }

        // phase 2: C += P @ v, warp tile 32x8
#pragma unroll
        for (int ks = 0; ks < 8; ks++) {
            int kb = ks * 8;
            uint32_t ah2[2][4], al2[2][4];
#pragma unroll
            for (int mt = 0; mt < 2; mt++) {
                int r = wm * 32 + mt * 16;
                float f0 = Ssm[(r + g) * 68 + kb + tg];
                float f1 = Ssm[(r + g + 8) * 68 + kb + tg];
                float f2 = Ssm[(r + g) * 68 + kb + tg + 4];
                float f3 = Ssm[(r + g + 8) * 68 + kb + tg + 4];
                split2(f0, ah2[mt][0], al2[mt][0]);
                split2(f1, ah2[mt][1], al2[mt][1]);
                split2(f2, ah2[mt][2], al2[mt][2]);
                split2(f3, ah2[mt][3], al2[mt][3]);
            }
            int c = wn * 8;
            uint32_t bh0 = vh[(kb + tg) * 33 + c + g];
            uint32_t bh1 = vh[(kb + tg + 4) * 33 + c + g];
            uint32_t bl0 = vl[(kb + tg) * 33 + c + g];
            uint32_t bl1 = vl[(kb + tg + 4) * 33 + c + g];
#pragma unroll
            for (int mt = 0; mt < 2; mt++) {
                mma8(cacc[mt], ah2[mt], bh0, bh1);
                mma8(cacc[mt], al2[mt], bh0, bh1);
                mma8(cacc[mt], ah2[mt], bl0, bl1);
            }
        }
    }

    // rowsum reduce
    ssum[myrow * 4 + myq] = srow;
    __syncthreads();
    if (tid < 64) {
        float s = ssum[tid * 4] + ssum[tid * 4 + 1] + ssum[tid * 4 + 2] + ssum[tid * 4 + 3];
        sinv[tid] = 1.f / (s + 1.f);
    }
    __syncthreads();

    // epilogue: out = C * inv - v
#pragma unroll
    for (int mt = 0; mt < 2; mt++) {
        int rl = wm * 32 + mt * 16 + g;
        int cl = wn * 8 + 2 * tg;
#pragma unroll
        for (int e = 0; e < 4; e++) {
            int rr = rl + (e >> 1) * 8;
            int cc = cl + (e & 1);
            size_t o = (size_t)(b * N_ + qb * 64 + rr) * D_ + h * DH_ + cc;
            cmv[o] = cacc[mt][e] * sinv[rr] - v_[o];
        }
    }
}

// ---------------- fused silu-gate + depthwise conv3 ----------------
__global__ void siluconv_kernel(const float* __restrict__ gu, const float* __restrict__ cw,
                                int kidx, float* __restrict__ out) {
    int idx = blockIdx.x * 256 + threadIdx.x;     // (b*N+n)*IN_ + i
    int i   = idx & (IN_ - 1);
    int bn  = idx >> 10;
    int n   = bn & (N_ - 1);
    const float* wp = cw + ((size_t)kidx * IN_ + i) * CK_;

    float gC = gu[(size_t)bn * (2 * IN_) + i];
    float uC = gu[(size_t)bn * (2 * IN_) + IN_ + i];
    float a = wp[1] * (gC / (1.f + expf(-gC)) * uC);
    if (n > 0) {
        float gm = gu[(size_t)(bn - 1) * (2 * IN_) + i];
        float um = gu[(size_t)(bn - 1) * (2 * IN_) + IN_ + i];
        a = fmaf(wp[0], gm / (1.f + expf(-gm)) * um, a);
    }
    if (n < N_ - 1) {
        float gp = gu[(size_t)(bn + 1) * (2 * IN_) + i];
        float up = gu[(size_t)(bn + 1) * (2 * IN_) + IN_ + i];
        a = fmaf(wp[2], gp / (1.f + expf(-gp)) * up, a);
    }
    out[idx] = a;
}

// ---------------- halt head ----------------
__global__ void halt_kernel(const float* __restrict__ qn, const float* __restrict__ hw,
                            const float* __restrict__ hb, float* __restrict__ out, int l4) {
    int b = blockIdx.x;
    int d = threadIdx.x;
    float s = 0.f;
    for (int n = 0; n < N_; n++) s += qn[(size_t)(b * N_ + n) * D_ + d];
    float p = (s * (1.f / N_)) * hw[d];
    float tot = blockReduceSum256(p);
    if (threadIdx.x == 0)
        out[l4 * B_ + b] = 1.f / (1.f + expf(-(tot + hb[0])));
}

// ---------------- host orchestration ----------------
static inline float* symaddr(const void* sym) {
    void* p = nullptr;
    cudaGetSymbolAddress(&p, sym);
    return (float*)p;
}

extern "C" void kernel_launch(void* const* d_in, const int* in_sizes, int n_in,
                              void* d_out, int out_size) {
    const int*   ids   = (const int*)  d_in[0];
    const float* emb   = (const float*)d_in[1];
    const float* pos   = (const float*)d_in[2];
    const float* in_w  = (const float*)d_in[3];
    const float* in_b  = (const float*)d_in[4];
    const float* Wq    = (const float*)d_in[5];
    const float* Wk    = (const float*)d_in[6];
    const float* Wv    = (const float*)d_in[7];
    const float* Wo    = (const float*)d_in[8];
    const float* dts   = (const float*)d_in[9];
    const float* Wup   = (const float*)d_in[10];
    const float* cw    = (const float*)d_in[11];
    const float* Wd    = (const float*)d_in[12];
    const float* n1w   = (const float*)d_in[13];
    const float* n1b   = (const float*)d_in[14];
    const float* n2w   = (const float*)d_in[15];
    const float* n2b   = (const float*)d_in[16];
    const float* fin_w = (const float*)d_in[17];
    const float* fin_b = (const float*)d_in[18];
    const float* haltw = (const float*)d_in[19];
    const float* haltb = (const float*)d_in[20];
    const float* lm_w  = (const float*)d_in[21];

    float* out        = (float*)d_out;
    float* out_logits = out;
    float* out_halts  = out + (size_t)out_size - (size_t)(MAXL_ - TRUNC_) * B_;

    float* pX   = symaddr(g_X);
    float* pQ   = symaddr(g_Q);
    float* pHc  = symaddr(g_Hc);
    float* pPq  = symaddr(g_pq);
    float* pPk  = symaddr(g_pk);
    float* pV   = symaddr(g_v);
    float* pCmv = symaddr(g_cmv);
    float* pHn  = symaddr(g_hn);
    float* pGU  = symaddr(g_gu);
    float* pHc2 = symaddr(g_hc2);
    float* pQn  = symaddr(g_qn);

    // allow >48KB dynamic smem (idempotent; host-side only, capture-safe)
    cudaFuncSetAttribute(gemm_tc<3>, cudaFuncAttributeMaxDynamicSharedMemorySize, GEMM_SMEM_3);
    cudaFuncSetAttribute(gemm_tc<1>, cudaFuncAttributeMaxDynamicSharedMemorySize, GEMM_SMEM_1);
    cudaFuncSetAttribute(attn_tc,    cudaFuncAttributeMaxDynamicSharedMemorySize, ATT_SMEM);

    // X = ln(emb[ids] + pos);  Q = X
    embed_kernel<<<BN_, 256>>>(ids, emb, pos, pX);
    ln_kernel<<<BN_, 256>>>(pX, in_w, in_b, nullptr, pX, pQ);

    const dim3 gDD(D_ / GBN, BN_ / GBM);            // (4, 16) D-wide GEMMs
    const dim3 gUP(2 * IN_ / GBN, BN_ / GBM);       // (32, 16) Wup
    const dim3 gLM(V_ / GBN, BN_ / GBM);            // (500, 16) lm head
    const int  ec = (BN_ * IN_) / 256;

    for (int l = 0; l < MAXL_; l++) {
        for (int k = 0; k < K_; k++) {
            // Hc = ln(Q; n1) + X
            ln_kernel<<<BN_, 256>>>(pQ, n1w + k * D_, n1b + k * D_, pX, pHc, nullptr);
            // pq/pk = elu(Hc@W)+1 ; v = Hc@Wv
            gemm_tc<3><<<gDD, 256, GEMM_SMEM_3>>>(pHc, Wq + (size_t)k * D_ * D_, pPq,
                                                  BN_, D_, D_, 1, nullptr, nullptr, 0);
            gemm_tc<3><<<gDD, 256, GEMM_SMEM_3>>>(pHc, Wk + (size_t)k * D_ * D_, pPk,
                                                  BN_, D_, D_, 1, nullptr, nullptr, 0);
            gemm_tc<3><<<gDD, 256, GEMM_SMEM_3>>>(pHc, Wv + (size_t)k * D_ * D_, pV,
                                                  BN_, D_, D_, 0, nullptr, nullptr, 0);
            // cmv = (relu(pq pk^T)^2 @ v) / (rowsum + 1) - v
            attn_tc<<<dim3(B_ * H_, N_ / 64), 256, ATT_SMEM>>>(pPq, pPk, pV, pCmv);
            // Q = Q + softplus(dt_k) * (cmv @ Wo)
            gemm_tc<3><<<gDD, 256, GEMM_SMEM_3>>>(pCmv, Wo + (size_t)k * D_ * D_, pQ,
                                                  BN_, D_, D_, 2, pQ, dts, k);
            // Hn = ln(Q; n2); GU = Hn @ Wup
            ln_kernel<<<BN_, 256>>>(pQ, n2w + k * D_, n2b + k * D_, nullptr, pHn, nullptr);
            gemm_tc<3><<<gUP, 256, GEMM_SMEM_3>>>(pHn, Wup + (size_t)k * D_ * 2 * IN_, pGU,
                                                  BN_, 2 * IN_, D_, 0, nullptr, nullptr, 0);
            // Hc2 = conv3(silu(G)*U); Q = Q + Hc2 @ Wd
            siluconv_kernel<<<ec, 256>>>(pGU, cw, k, pHc2);
            gemm_tc<3><<<gDD, 256, GEMM_SMEM_3>>>(pHc2, Wd + (size_t)k * IN_ * D_, pQ,
                                                  BN_, D_, IN_, 3, pQ, nullptr, 0);
        }
        if (l >= TRUNC_) {
            int l4 = l - TRUNC_;
            ln_kernel<<<BN_, 256>>>(pQ, fin_w, fin_b, nullptr, pQn, nullptr);
            halt_kernel<<<B_, 256>>>(pQn, haltw, haltb, out_halts, l4);
            gemm_tc<1><<<gLM, 256, GEMM_SMEM_1>>>(pQn, lm_w,
                                                  out_logits + (size_t)l4 * BN_ * V_,
                                                  BN_, V_, D_, 0, nullptr, nullptr, 0);
        }
    }
}

// round 5
// speedup vs baseline: 1.6400x; 1.6400x over previous
#include <cuda_runtime.h>
#include <cuda_bf16.h>
#include <math.h>
#include <stdint.h>

// ---------------- model constants ----------------
#define B_    2
#define N_    1024
#define D_    256
#define H_    8
#define DH_   32
#define K_    4
#define IN_   1024
#define V_    32000
#define CK_   3
#define MAXL_ 8
#define TRUNC_ 4
#define BN_   (B_ * N_)
#define QKVS  (3 * D_)      // row stride of fused qkv buffer

// ---------------- scratch (device globals, no allocs) ----------------
__device__ float g_X  [BN_ * D_];
__device__ float g_Q  [BN_ * D_];
__device__ float g_Hc [BN_ * D_];
__device__ float g_qkv[BN_ * QKVS];
__device__ float g_cmv[BN_ * D_];
__device__ float g_hn [BN_ * D_];
__device__ float g_gu [BN_ * 2 * IN_];
__device__ float g_hc2[BN_ * IN_];
__device__ float g_qn [BN_ * D_];

// ---------------- bf16 helpers ----------------
__device__ __forceinline__ uint32_t pack_bf2(float a, float b) {
    __nv_bfloat162 t = __floats2bfloat162_rn(a, b);   // x = a (low), y = b (high)
    return *reinterpret_cast<uint32_t*>(&t);
}
__device__ __forceinline__ void split_bf(float v, __nv_bfloat16& h, __nv_bfloat16& l) {
    h = __float2bfloat16_rn(v);
    l = __float2bfloat16_rn(v - __bfloat162float(h));
}

__device__ __forceinline__ void mma16(float* c, const uint32_t* a, uint32_t b0, uint32_t b1) {
    asm volatile("mma.sync.aligned.m16n8k16.row.col.f32.bf16.bf16.f32 "
                 "{%0,%1,%2,%3}, {%4,%5,%6,%7}, {%8,%9}, {%0,%1,%2,%3};"
                 : "+f"(c[0]), "+f"(c[1]), "+f"(c[2]), "+f"(c[3])
                 : "r"(a[0]), "r"(a[1]), "r"(a[2]), "r"(a[3]), "r"(b0), "r"(b1));
}

// ---------------- tf32 helpers (LM head only) ----------------
__device__ __forceinline__ void split2(float x, uint32_t& hi, uint32_t& lo) {
    uint32_t h;
    asm("cvt.rna.tf32.f32 %0, %1;" : "=r"(h) : "f"(x));
    float r = x - __uint_as_float(h);
    uint32_t l;
    asm("cvt.rna.tf32.f32 %0, %1;" : "=r"(l) : "f"(r));
    hi = h; lo = l;
}
__device__ __forceinline__ void mma8(float* c, const uint32_t* a, uint32_t b0, uint32_t b1) {
    asm volatile("mma.sync.aligned.m16n8k8.row.col.f32.tf32.tf32.f32 "
                 "{%0,%1,%2,%3}, {%4,%5,%6,%7}, {%8,%9}, {%0,%1,%2,%3};"
                 : "+f"(c[0]), "+f"(c[1]), "+f"(c[2]), "+f"(c[3])
                 : "r"(a[0]), "r"(a[1]), "r"(a[2]), "r"(a[3]), "r"(b0), "r"(b1));
}

// ---------------- misc helpers ----------------
__device__ __forceinline__ float blockReduceSum256(float v) {
    __shared__ float sh[8];
    int lane = threadIdx.x & 31;
    int wid  = threadIdx.x >> 5;
#pragma unroll
    for (int o = 16; o > 0; o >>= 1) v += __shfl_down_sync(0xffffffffu, v, o);
    __syncthreads();
    if (lane == 0) sh[wid] = v;
    __syncthreads();
    float t = 0.f;
#pragma unroll
    for (int i = 0; i < 8; i++) t += sh[i];
    return t;
}

// ---------------- embedding + positional ----------------
__global__ void embed_kernel(const int* __restrict__ ids,
                             const float* __restrict__ emb,
                             const float* __restrict__ pos,
                             float* __restrict__ X) {
    int row = blockIdx.x;
    int d   = threadIdx.x;
    int n   = row & (N_ - 1);
    int id  = ids[row];
    X[(size_t)row * D_ + d] = emb[(size_t)id * D_ + d] + pos[(size_t)n * D_ + d];
}

// ---------------- layernorm ----------------
__global__ void ln_kernel(const float* __restrict__ in,
                          const float* __restrict__ w,
                          const float* __restrict__ b,
                          const float* __restrict__ addX,
                          float* __restrict__ out,
                          float* __restrict__ out2) {
    int row = blockIdx.x;
    int d   = threadIdx.x;
    float x  = in[(size_t)row * D_ + d];
    float mu = blockReduceSum256(x) * (1.f / D_);
    float dx = x - mu;
    float var = blockReduceSum256(dx * dx) * (1.f / D_);
    float y = dx * rsqrtf(var + 1e-5f) * w[d] + b[d];
    if (addX) y += addX[(size_t)row * D_ + d];
    out[(size_t)row * D_ + d] = y;
    if (out2) out2[(size_t)row * D_ + d] = y;
}

// ============================================================================
// bf16x3 GEMM, 64x64x32 tiles, 256 threads (8 warps: 2m x 4n, warp tile 32x16)
// Supports up to 3 weight matrices (QKV fusion): block column group selects B.
// epi: 0 none, 1 elu(x)+1, 2 aux + softplus(dts[kidx])*x, 3 aux + x
// ============================================================================
#define GB3_SMEM ((4 * 64 * 17) * 4)

__global__ void __launch_bounds__(256)
gemm_b3(const float* __restrict__ A,
        const float* __restrict__ B0, const float* __restrict__ B1,
        const float* __restrict__ B2,
        float* __restrict__ C, int Kd, int N, int nblk, int ldc,
        int e0, int e1, int e2,
        const float* __restrict__ aux, const float* __restrict__ dts, int kidx)
{
    extern __shared__ uint32_t sh[];
    uint32_t* Ah = sh;                 // [64][17] packed bf16 pairs (k-major)
    uint32_t* Al = Ah + 64 * 17;
    uint32_t* Bh = Al + 64 * 17;       // [64 n][17] pairs along k
    uint32_t* Bl = Bh + 64 * 17;
    __nv_bfloat16* Bhb = (__nv_bfloat16*)Bh;
    __nv_bfloat16* Blb = (__nv_bfloat16*)Bl;

    const int tid  = threadIdx.x;
    const int lane = tid & 31;
    const int wid  = tid >> 5;
    const int g  = lane >> 2, tg = lane & 3;
    const int wm = wid & 1, wn = wid >> 1;     // 2 (m) x 4 (n)

    const int bx    = blockIdx.x;
    const int which = bx / nblk;
    const int bxl   = bx - which * nblk;
    const int col0  = bxl * 64;                  // within selected B
    const int ocol0 = which * N + col0;          // within C
    const int row0  = blockIdx.y * 64;
    const float* Bm = (which == 0) ? B0 : (which == 1) ? B1 : B2;
    const int epi   = (which == 0) ? e0 : (which == 1) ? e1 : e2;

    float acc[2][2][4];
#pragma unroll
    for (int a = 0; a < 2; a++)
#pragma unroll
        for (int b = 0; b < 2; b++)
#pragma unroll
            for (int c = 0; c < 4; c++) acc[a][b][c] = 0.f;

    for (int kt = 0; kt < Kd; kt += 32) {
        __syncthreads();
        // A tile 64x32 -> Ah/Al packed pairs (2 float4 per thread)
#pragma unroll
        for (int it = 0; it < 2; it++) {
            int flat = it * 256 + tid;
            int m  = flat >> 3;
            int kq = (flat & 7) << 2;
            float4 av = *(const float4*)(A + (size_t)(row0 + m) * Kd + kt + kq);
            __nv_bfloat16 h0, l0, h1, l1, h2, l2, h3, l3;
            split_bf(av.x, h0, l0); split_bf(av.y, h1, l1);
            split_bf(av.z, h2, l2); split_bf(av.w, h3, l3);
            int base = m * 17 + (kq >> 1);
            Ah[base]     = pack_bf2(__bfloat162float(h0), __bfloat162float(h1));
            Ah[base + 1] = pack_bf2(__bfloat162float(h2), __bfloat162float(h3));
            Al[base]     = pack_bf2(__bfloat162float(l0), __bfloat162float(l1));
            Al[base + 1] = pack_bf2(__bfloat162float(l2), __bfloat162float(l3));
        }
        // B tile 32k x 64n -> transposed [n][k] bf16 (2 float4 per thread)
#pragma unroll
        for (int it = 0; it < 2; it++) {
            int flat = it * 256 + tid;
            int kk = flat >> 4;               // k row 0..31
            int nq = (flat & 15) << 2;        // n col
            float4 bv = *(const float4*)(Bm + (size_t)(kt + kk) * N + col0 + nq);
            float vv[4] = {bv.x, bv.y, bv.z, bv.w};
#pragma unroll
            for (int j = 0; j < 4; j++) {
                __nv_bfloat16 h, l; split_bf(vv[j], h, l);
                Bhb[(nq + j) * 34 + kk] = h;
                Blb[(nq + j) * 34 + kk] = l;
            }
        }
        __syncthreads();

#pragma unroll
        for (int ks = 0; ks < 2; ks++) {        // two k16 slices
            int kb = ks * 8;
            uint32_t ah[2][4], al[2][4];
#pragma unroll
            for (int mt = 0; mt < 2; mt++) {
                int r = wm * 32 + mt * 16;
                ah[mt][0] = Ah[(r + g) * 17 + kb + tg];
                ah[mt][1] = Ah[(r + g + 8) * 17 + kb + tg];
                ah[mt][2] = Ah[(r + g) * 17 + kb + tg + 4];
                ah[mt][3] = Ah[(r + g + 8) * 17 + kb + tg + 4];
                al[mt][0] = Al[(r + g) * 17 + kb + tg];
                al[mt][1] = Al[(r + g + 8) * 17 + kb + tg];
                al[mt][2] = Al[(r + g) * 17 + kb + tg + 4];
                al[mt][3] = Al[(r + g + 8) * 17 + kb + tg + 4];
            }
#pragma unroll
            for (int nt = 0; nt < 2; nt++) {
                int c = wn * 16 + nt * 8;
                uint32_t bh0 = Bh[(c + g) * 17 + kb + tg];
                uint32_t bh1 = Bh[(c + g) * 17 + kb + tg + 4];
                uint32_t bl0 = Bl[(c + g) * 17 + kb + tg];
                uint32_t bl1 = Bl[(c + g) * 17 + kb + tg + 4];
#pragma unroll
                for (int mt = 0; mt < 2; mt++) {
                    mma16(acc[mt][nt], ah[mt], bh0, bh1);
                    mma16(acc[mt][nt], al[mt], bh0, bh1);
                    mma16(acc[mt][nt], ah[mt], bl0, bl1);
                }
            }
        }
    }

    float sp = (epi == 2) ? log1pf(expf(dts[kidx])) : 0.f;
#pragma unroll
    for (int mt = 0; mt < 2; mt++) {
#pragma unroll
        for (int nt = 0; nt < 2; nt++) {
            int r = row0 + wm * 32 + mt * 16 + g;
            int c = ocol0 + wn * 16 + nt * 8 + 2 * tg;
#pragma unroll
            for (int e = 0; e < 4; e++) {
                int rr = r + (e >> 1) * 8;
                int cc = c + (e & 1);
                size_t o = (size_t)rr * ldc + cc;
                float x = acc[mt][nt][e];
                float y;
                if (epi == 1)      y = (x > 0.f) ? (x + 1.f) : expf(x);
                else if (epi == 2) y = aux[o] + sp * x;
                else if (epi == 3) y = aux[o] + x;
                else               y = x;
                C[o] = y;
            }
        }
    }
}

// ============================================================================
// bf16x3 attention: per (b,h,q64): S = pq@pk^T, W = relu(S)^2, C = W@v,
// out = C/(rowsum+1) - v.  pq/pk/v strided (QKVS) from fused buffer.
// ============================================================================
#define ATT_SMEM ((4 * 64 * 17 + 2 * 32 * 33 + 64 * 68 + 256 + 64) * 4)

__global__ void __launch_bounds__(256)
attn_tc(const float* __restrict__ pq_, const float* __restrict__ pk_,
        const float* __restrict__ v_, float* __restrict__ cmv)
{
    extern __shared__ uint32_t sh[];
    uint32_t* qh = sh;                  // [64][17] pairs along dh
    uint32_t* ql = qh + 64 * 17;
    uint32_t* kh = ql + 64 * 17;        // [64 tok][17] pairs along dh
    uint32_t* kl = kh + 64 * 17;
    uint32_t* vh = kl + 64 * 17;        // [32 dh][33] pairs along token
    uint32_t* vl = vh + 32 * 33;
    float* Ssm  = (float*)(vl + 32 * 33);  // 64 x 68
    float* ssum = Ssm + 64 * 68;           // 256
    float* sinv = ssum + 256;              // 64
    __nv_bfloat16* vhb = (__nv_bfloat16*)vh;
    __nv_bfloat16* vlb = (__nv_bfloat16*)vl;

    const int tid  = threadIdx.x;
    const int lane = tid & 31, wid = tid >> 5;
    const int g = lane >> 2, tg = lane & 3;
    const int wm = wid & 1, wn = wid >> 1;   // 2 (m) x 4 (n)
    const int bh = blockIdx.x;
    const int b = bh >> 3, h = bh & 7;
    const int qb = blockIdx.y;

    // load pq tile (64 x 32), split+pack
#pragma unroll
    for (int it = 0; it < 2; it++) {
        int flat = it * 256 + tid;
        int r  = flat >> 3;
        int dq = (flat & 7) << 2;
        float4 av = *(const float4*)(pq_ + (size_t)(b * N_ + qb * 64 + r) * QKVS + h * DH_ + dq);
        __nv_bfloat16 h0, l0, h1, l1, h2, l2, h3, l3;
        split_bf(av.x, h0, l0); split_bf(av.y, h1, l1);
        split_bf(av.z, h2, l2); split_bf(av.w, h3, l3);
        int base = r * 17 + (dq >> 1);
        qh[base]     = pack_bf2(__bfloat162float(h0), __bfloat162float(h1));
        qh[base + 1] = pack_bf2(__bfloat162float(h2), __bfloat162float(h3));
        ql[base]     = pack_bf2(__bfloat162float(l0), __bfloat162float(l1));
        ql[base + 1] = pack_bf2(__bfloat162float(l2), __bfloat162float(l3));
    }

    float cacc[2][4];
#pragma unroll
    for (int mt = 0; mt < 2; mt++)
#pragma unroll
        for (int e = 0; e < 4; e++) cacc[mt][e] = 0.f;
    float srow = 0.f;
    const int myrow = tid >> 2, myq = tid & 3;

    for (int kt = 0; kt < N_; kt += 64) {
        __syncthreads();
        // load pk (pairs along dh) and v (transposed: pairs along token)
#pragma unroll
        for (int it = 0; it < 2; it++) {
            int flat = it * 256 + tid;
            int r  = flat >> 3;
            int dq = (flat & 7) << 2;
            size_t go = (size_t)(b * N_ + kt + r) * QKVS + h * DH_ + dq;
            float4 kv4 = *(const float4*)(pk_ + go);
            float4 vv4 = *(const float4*)(v_ + go);
            {
                __nv_bfloat16 h0, l0, h1, l1, h2, l2, h3, l3;
                split_bf(kv4.x, h0, l0); split_bf(kv4.y, h1, l1);
                split_bf(kv4.z, h2, l2); split_bf(kv4.w, h3, l3);
                int base = r * 17 + (dq >> 1);
                kh[base]     = pack_bf2(__bfloat162float(h0), __bfloat162float(h1));
                kh[base + 1] = pack_bf2(__bfloat162float(h2), __bfloat162float(h3));
                kl[base]     = pack_bf2(__bfloat162float(l0), __bfloat162float(l1));
                kl[base + 1] = pack_bf2(__bfloat162float(l2), __bfloat162float(l3));
            }
            {
                float vv[4] = {vv4.x, vv4.y, vv4.z, vv4.w};
#pragma unroll
                for (int j = 0; j < 4; j++) {
                    __nv_bfloat16 hh, ll; split_bf(vv[j], hh, ll);
                    vhb[(dq + j) * 66 + r] = hh;
                    vlb[(dq + j) * 66 + r] = ll;
                }
            }
        }
        __syncthreads();

        // phase 1: S = pq @ pk^T, warp tile 32x16
        float sacc[2][2][4];
#pragma unroll
        for (int mt = 0; mt < 2; mt++)
#pragma unroll
            for (int nt = 0; nt < 2; nt++)
#pragma unroll
                for (int e = 0; e < 4; e++) sacc[mt][nt][e] = 0.f;

#pragma unroll
        for (int ks = 0; ks < 2; ks++) {        // dh = 32 -> two k16 slices
            int kb = ks * 8;
            uint32_t ah[2][4], al[2][4];
#pragma unroll
            for (int mt = 0; mt < 2; mt++) {
                int r = wm * 32 + mt * 16;
                ah[mt][0] = qh[(r + g) * 17 + kb + tg];
                ah[mt][1] = qh[(r + g + 8) * 17 + kb + tg];
                ah[mt][2] = qh[(r + g) * 17 + kb + tg + 4];
                ah[mt][3] = qh[(r + g + 8) * 17 + kb + tg + 4];
                al[mt][0] = ql[(r + g) * 17 + kb + tg];
                al[mt][1] = ql[(r + g + 8) * 17 + kb + tg];
                al[mt][2] = ql[(r + g) * 17 + kb + tg + 4];
                al[mt][3] = ql[(r + g + 8) * 17 + kb + tg + 4];
            }
#pragma unroll
            for (int nt = 0; nt < 2; nt++) {
                int c = wn * 16 + nt * 8;
                uint32_t bh0 = kh[(c + g) * 17 + kb + tg];
                uint32_t bh1 = kh[(c + g) * 17 + kb + tg + 4];
                uint32_t bl0 = kl[(c + g) * 17 + kb + tg];
                uint32_t bl1 = kl[(c + g) * 17 + kb + tg + 4];
#pragma unroll
                for (int mt = 0; mt < 2; mt++) {
                    mma16(sacc[mt][nt], ah[mt], bh0, bh1);
                    mma16(sacc[mt][nt], al[mt], bh0, bh1);
                    mma16(sacc[mt][nt], ah[mt], bl0, bl1);
                }
            }
        }
        // relu^2 -> Ssm
#pragma unroll
        for (int mt = 0; mt < 2; mt++)
#pragma unroll
            for (int nt = 0; nt < 2; nt++) {
                int r = wm * 32 + mt * 16 + g;
                int c = wn * 16 + nt * 8 + 2 * tg;
#pragma unroll
                for (int e = 0; e < 4; e++) {
                    int rr = r + (e >> 1) * 8, cc = c + (e & 1);
                    float w = fmaxf(sacc[mt][nt][e], 0.f);
                    Ssm[rr * 68 + cc] = w * w;
                }
            }
        __syncthreads();

        // rowsum partial
        {
            const float* spp = Ssm + myrow * 68 + myq * 16;
            float t = 0.f;
#pragma unroll
            for (int j = 0; j < 16; j++) t += spp[j];
            srow += t;
        }

        // phase 2: C += P @ v, warp tile 32 rows x 8 dh cols
#pragma unroll
        for (int ks = 0; ks < 4; ks++) {       // token = 64 -> four k16 slices
            int kb = ks * 16;
            uint32_t ah2[2][4], al2[2][4];
#pragma unroll
            for (int mt = 0; mt < 2; mt++) {
                int r = wm * 32 + mt * 16;
                const float* S0 = Ssm + (r + g) * 68 + kb;
                const float* S1 = Ssm + (r + g + 8) * 68 + kb;
                float f0a = S0[2 * tg],     f0b = S0[2 * tg + 1];
                float f1a = S1[2 * tg],     f1b = S1[2 * tg + 1];
                float f2a = S0[2 * tg + 8], f2b = S0[2 * tg + 9];
                float f3a = S1[2 * tg + 8], f3b = S1[2 * tg + 9];
                __nv_bfloat16 hh, ll;
                float h0a, l0a, h0b, l0b;
                split_bf(f0a, hh, ll); h0a = __bfloat162float(hh); l0a = __bfloat162float(ll);
                split_bf(f0b, hh, ll); h0b = __bfloat162float(hh); l0b = __bfloat162float(ll);
                ah2[mt][0] = pack_bf2(h0a, h0b); al2[mt][0] = pack_bf2(l0a, l0b);
                split_bf(f1a, hh, ll); h0a = __bfloat162float(hh); l0a = __bfloat162float(ll);
                split_bf(f1b, hh, ll); h0b = __bfloat162float(hh); l0b = __bfloat162float(ll);
                ah2[mt][1] = pack_bf2(h0a, h0b); al2[mt][1] = pack_bf2(l0a, l0b);
                split_bf(f2a, hh, ll); h0a = __bfloat162float(hh); l0a = __bfloat162float(ll);
                split_bf(f2b, hh, ll); h0b = __bfloat162float(hh); l0b = __bfloat162float(ll);
                ah2[mt][2] = pack_bf2(h0a, h0b); al2[mt][2] = pack_bf2(l0a, l0b);
                split_bf(f3a, hh, ll); h0a = __bfloat162float(hh); l0a = __bfloat162float(ll);
                split_bf(f3b, hh, ll); h0b = __bfloat162float(hh); l0b = __bfloat162float(ll);
                ah2[mt][3] = pack_bf2(h0a, h0b); al2[mt][3] = pack_bf2(l0a, l0b);
            }
            int c = wn * 8;
            uint32_t bh0 = vh[(c + g) * 33 + ks * 8 + tg];
            uint32_t bh1 = vh[(c + g) * 33 + ks * 8 + tg + 4];
            uint32_t bl0 = vl[(c + g) * 33 + ks * 8 + tg];
            uint32_t bl1 = vl[(c + g) * 33 + ks * 8 + tg + 4];
#pragma unroll
            for (int mt = 0; mt < 2; mt++) {
                mma16(cacc[mt], ah2[mt], bh0, bh1);
                mma16(cacc[mt], al2[mt], bh0, bh1);
                mma16(cacc[mt], ah2[mt], bl0, bl1);
            }
        }
    }

    // rowsum reduce
    ssum[myrow * 4 + myq] = srow;
    __syncthreads();
    if (tid < 64) {
        float s = ssum[tid * 4] + ssum[tid * 4 + 1] + ssum[tid * 4 + 2] + ssum[tid * 4 + 3];
        sinv[tid] = 1.f / (s + 1.f);
    }
    __syncthreads();

    // epilogue: out = C * inv - v
#pragma unroll
    for (int mt = 0; mt < 2; mt++) {
        int rl = wm * 32 + mt * 16 + g;
        int cl = wn * 8 + 2 * tg;
#pragma unroll
        for (int e = 0; e < 4; e++) {
            int rr = rl + (e >> 1) * 8;
            int cc = cl + (e & 1);
            size_t vo = (size_t)(b * N_ + qb * 64 + rr) * QKVS + h * DH_ + cc;
            size_t oo = (size_t)(b * N_ + qb * 64 + rr) * D_ + h * DH_ + cc;
            cmv[oo] = cacc[mt][e] * sinv[rr] - v_[vo];
        }
    }
}

// ============================================================================
// tf32 x1 GEMM (LM head only): 128x64x32 tiles
// ============================================================================
#define GEMM_SMEM_1 (((128 * 33) + (32 * 65)) * 4)

__global__ void __launch_bounds__(256, 2)
gemm_lm(const float* __restrict__ A, const float* __restrict__ Bm, float* __restrict__ C,
        int N, int Kd)
{
    extern __shared__ uint32_t sh[];
    uint32_t* Ah = sh;                      // 128*33
    uint32_t* Bh = Ah + 128 * 33;           // 32*65

    const int tid  = threadIdx.x;
    const int lane = tid & 31;
    const int wid  = tid >> 5;
    const int g  = lane >> 2, tg = lane & 3;
    const int wm = wid & 3,   wn = wid >> 2;          // 4 (m) x 2 (n)
    const int row0 = blockIdx.y * 128;
    const int col0 = blockIdx.x * 64;

    float acc[2][4][4];
#pragma unroll
    for (int a = 0; a < 2; a++)
#pragma unroll
        for (int b = 0; b < 4; b++)
#pragma unroll
            for (int c = 0; c < 4; c++) acc[a][b][c] = 0.f;

    for (int kt = 0; kt < Kd; kt += 32) {
        __syncthreads();
#pragma unroll
        for (int it = 0; it < 4; it++) {
            int flat = it * 256 + tid;
            int m  = flat >> 3;
            int kq = (flat & 7) << 2;
            float4 av = *(const float4*)(A + (size_t)(row0 + m) * Kd + kt + kq);
            float vv[4] = {av.x, av.y, av.z, av.w};
#pragma unroll
            for (int j = 0; j < 4; j++) {
                uint32_t hi, lo; split2(vv[j], hi, lo);
                Ah[m * 33 + kq + j] = hi;
            }
        }
#pragma unroll
        for (int it = 0; it < 2; it++) {
            int flat = it * 256 + tid;
            int kk = flat >> 4;
            int nq = (flat & 15) << 2;
            float4 bv = *(const float4*)(Bm + (size_t)(kt + kk) * N + col0 + nq);
            float vv[4] = {bv.x, bv.y, bv.z, bv.w};
#pragma unroll
            for (int j = 0; j < 4; j++) {
                uint32_t hi, lo; split2(vv[j], hi, lo);
                Bh[kk * 65 + nq + j] = hi;
            }
        }
        __syncthreads();

#pragma unroll
        for (int ks = 0; ks < 4; ks++) {
            int kb = ks * 8;
            uint32_t ah[2][4];
#pragma unroll
            for (int mt = 0; mt < 2; mt++) {
                int r = wm * 32 + mt * 16;
                ah[mt][0] = Ah[(r + g) * 33 + kb + tg];
                ah[mt][1] = Ah[(r + g + 8) * 33 + kb + tg];
                ah[mt][2] = Ah[(r + g) * 33 + kb + tg + 4];
                ah[mt][3] = Ah[(r + g + 8) * 33 + kb + tg + 4];
            }
#pragma unroll
            for (int nt = 0; nt < 4; nt++) {
                int c = wn * 32 + nt * 8;
                uint32_t bh0 = Bh[(kb + tg) * 65 + c + g];
                uint32_t bh1 = Bh[(kb + tg + 4) * 65 + c + g];
#pragma unroll
                for (int mt = 0; mt < 2; mt++) mma8(acc[mt][nt], ah[mt], bh0, bh1);
            }
        }
    }

#pragma unroll
    for (int mt = 0; mt < 2; mt++) {
#pragma unroll
        for (int nt = 0; nt < 4; nt++) {
            int r = row0 + wm * 32 + mt * 16 + g;
            int c = col0 + wn * 32 + nt * 8 + 2 * tg;
#pragma unroll
            for (int e = 0; e < 4; e++) {
                int rr = r + (e >> 1) * 8;
                int cc = c + (e & 1);
                C[(size_t)rr * N + cc] = acc[mt][nt][e];
            }
        }
    }
}

// ---------------- fused silu-gate + depthwise conv3 ----------------
__global__ void siluconv_kernel(const float* __restrict__ gu, const float* __restrict__ cw,
                                int kidx, float* __restrict__ out) {
    int idx = blockIdx.x * 256 + threadIdx.x;
    int i   = idx & (IN_ - 1);
    int bn  = idx >> 10;
    int n   = bn & (N_ - 1);
    const float* wp = cw + ((size_t)kidx * IN_ + i) * CK_;

    float gC = gu[(size_t)bn * (2 * IN_) + i];
    float uC = gu[(size_t)bn * (2 * IN_) + IN_ + i];
    float a = wp[1] * (gC / (1.f + expf(-gC)) * uC);
    if (n > 0) {
        float gm = gu[(size_t)(bn - 1) * (2 * IN_) + i];
        float um = gu[(size_t)(bn - 1) * (2 * IN_) + IN_ + i];
        a = fmaf(wp[0], gm / (1.f + expf(-gm)) * um, a);
    }
    if (n < N_ - 1) {
        float gp = gu[(size_t)(bn + 1) * (2 * IN_) + i];
        float up = gu[(size_t)(bn + 1) * (2 * IN_) + IN_ + i];
        a = fmaf(wp[2], gp / (1.f + expf(-gp)) * up, a);
    }
    out[idx] = a;
}

// ---------------- halt head ----------------
__global__ void halt_kernel(const float* __restrict__ qn, const float* __restrict__ hw,
                            const float* __restrict__ hb, float* __restrict__ out, int l4) {
    int b = blockIdx.x;
    int d = threadIdx.x;
    float s = 0.f;
    for (int n = 0; n < N_; n++) s += qn[(size_t)(b * N_ + n) * D_ + d];
    float p = (s * (1.f / N_)) * hw[d];
    float tot = blockReduceSum256(p);
    if (threadIdx.x == 0)
        out[l4 * B_ + b] = 1.f / (1.f + expf(-(tot + hb[0])));
}

// ---------------- host orchestration ----------------
static inline float* symaddr(const void* sym) {
    void* p = nullptr;
    cudaGetSymbolAddress(&p, sym);
    return (float*)p;
}

extern "C" void kernel_launch(void* const* d_in, const int* in_sizes, int n_in,
                              void* d_out, int out_size) {
    const int*   ids   = (const int*)  d_in[0];
    const float* emb   = (const float*)d_in[1];
    const float* pos   = (const float*)d_in[2];
    const float* in_w  = (const float*)d_in[3];
    const float* in_b  = (const float*)d_in[4];
    const float* Wq    = (const float*)d_in[5];
    const float* Wk    = (const float*)d_in[6];
    const float* Wv    = (const float*)d_in[7];
    const float* Wo    = (const float*)d_in[8];
    const float* dts   = (const float*)d_in[9];
    const float* Wup   = (const float*)d_in[10];
    const float* cw    = (const float*)d_in[11];
    const float* Wd    = (const float*)d_in[12];
    const float* n1w   = (const float*)d_in[13];
    const float* n1b   = (const float*)d_in[14];
    const float* n2w   = (const float*)d_in[15];
    const float* n2b   = (const float*)d_in[16];
    const float* fin_w = (const float*)d_in[17];
    const float* fin_b = (const float*)d_in[18];
    const float* haltw = (const float*)d_in[19];
    const float* haltb = (const float*)d_in[20];
    const float* lm_w  = (const float*)d_in[21];

    float* out        = (float*)d_out;
    float* out_logits = out;
    float* out_halts  = out + (size_t)out_size - (size_t)(MAXL_ - TRUNC_) * B_;

    float* pX   = symaddr(g_X);
    float* pQ   = symaddr(g_Q);
    float* pHc  = symaddr(g_Hc);
    float* pQKV = symaddr(g_qkv);
    float* pCmv = symaddr(g_cmv);
    float* pHn  = symaddr(g_hn);
    float* pGU  = symaddr(g_gu);
    float* pHc2 = symaddr(g_hc2);
    float* pQn  = symaddr(g_qn);

    cudaFuncSetAttribute(gemm_b3, cudaFuncAttributeMaxDynamicSharedMemorySize, GB3_SMEM);
    cudaFuncSetAttribute(attn_tc, cudaFuncAttributeMaxDynamicSharedMemorySize, ATT_SMEM);
    cudaFuncSetAttribute(gemm_lm, cudaFuncAttributeMaxDynamicSharedMemorySize, GEMM_SMEM_1);

    // X = ln(emb[ids] + pos);  Q = X
    embed_kernel<<<BN_, 256>>>(ids, emb, pos, pX);
    ln_kernel<<<BN_, 256>>>(pX, in_w, in_b, nullptr, pX, pQ);

    const dim3 gQKV(12, BN_ / 64);      // 3 matrices x 4 col blocks, 32 row blocks
    const dim3 gDD(4, BN_ / 64);        // N=256
    const dim3 gUP(32, BN_ / 64);       // N=2048
    const dim3 gLM(V_ / 64, BN_ / 128); // (500, 16)
    const int  ec = (BN_ * IN_) / 256;

    for (int l = 0; l < MAXL_; l++) {
        for (int k = 0; k < K_; k++) {
            // Hc = ln(Q; n1) + X
            ln_kernel<<<BN_, 256>>>(pQ, n1w + k * D_, n1b + k * D_, pX, pHc, nullptr);
            // fused qkv: [pq | pk | v] = [elu+1(Hc@Wq) | elu+1(Hc@Wk) | Hc@Wv]
            gemm_b3<<<gQKV, 256, GB3_SMEM>>>(pHc,
                                             Wq + (size_t)k * D_ * D_,
                                             Wk + (size_t)k * D_ * D_,
                                             Wv + (size_t)k * D_ * D_,
                                             pQKV, D_, D_, 4, QKVS,
                                             1, 1, 0, nullptr, nullptr, 0);
            // cmv = (relu(pq pk^T)^2 @ v) / (rowsum + 1) - v
            attn_tc<<<dim3(B_ * H_, N_ / 64), 256, ATT_SMEM>>>(pQKV, pQKV + D_,
                                                               pQKV + 2 * D_, pCmv);
            // Q = Q + softplus(dt_k) * (cmv @ Wo)
            gemm_b3<<<gDD, 256, GB3_SMEM>>>(pCmv, Wo + (size_t)k * D_ * D_,
                                            nullptr, nullptr, pQ, D_, D_, 4, D_,
                                            2, 2, 2, pQ, dts, k);
            // Hn = ln(Q; n2); GU = Hn @ Wup
            ln_kernel<<<BN_, 256>>>(pQ, n2w + k * D_, n2b + k * D_, nullptr, pHn, nullptr);
            gemm_b3<<<gUP, 256, GB3_SMEM>>>(pHn, Wup + (size_t)k * D_ * 2 * IN_,
                                            nullptr, nullptr, pGU, D_, 2 * IN_, 32, 2 * IN_,
                                            0, 0, 0, nullptr, nullptr, 0);
            // Hc2 = conv3(silu(G)*U); Q = Q + Hc2 @ Wd
            siluconv_kernel<<<ec, 256>>>(pGU, cw, k, pHc2);
            gemm_b3<<<gDD, 256, GB3_SMEM>>>(pHc2, Wd + (size_t)k * IN_ * D_,
                                            nullptr, nullptr, pQ, IN_, D_, 4, D_,
                                            3, 3, 3, pQ, nullptr, 0);
        }
        if (l >= TRUNC_) {
            int l4 = l - TRUNC_;
            ln_kernel<<<BN_, 256>>>(pQ, fin_w, fin_b, nullptr, pQn, nullptr);
            halt_kernel<<<B_, 256>>>(pQn, haltw, haltb, out_halts, l4);
            gemm_lm<<<gLM, 256, GEMM_SMEM_1>>>(pQn, lm_w,
                                               out_logits + (size_t)l4 * BN_ * V_,
                                               V_, D_);
        }
    }
}

// round 6
// speedup vs baseline: 1.6454x; 1.0033x over previous
#include <cuda_runtime.h>
#include <cuda_bf16.h>
#include <math.h>
#include <stdint.h>

// ---------------- model constants ----------------
#define B_    2
#define N_    1024
#define D_    256
#define H_    8
#define DH_   32
#define K_    4
#define IN_   1024
#define V_    32000
#define CK_   3
#define MAXL_ 8
#define TRUNC_ 4
#define BN_   (B_ * N_)
#define QKVS  (3 * D_)      // row stride of fused qkv buffer

// ---------------- scratch (device globals, no allocs) ----------------
__device__ float g_X  [BN_ * D_];
__device__ float g_Q  [BN_ * D_];
__device__ float g_Hc [BN_ * D_];
__device__ float g_qkv[BN_ * QKVS];
__device__ float g_cmv[BN_ * D_];
__device__ float g_hn [BN_ * D_];
__device__ float g_gu [BN_ * 2 * IN_];
__device__ float g_hc2[BN_ * IN_];
__device__ float g_qn [BN_ * D_];

// ---------------- bf16 helpers ----------------
__device__ __forceinline__ uint32_t pack_bf2(float a, float b) {
    __nv_bfloat162 t = __floats2bfloat162_rn(a, b);   // x = a (low), y = b (high)
    return *reinterpret_cast<uint32_t*>(&t);
}
__device__ __forceinline__ void split_bf(float v, __nv_bfloat16& h, __nv_bfloat16& l) {
    h = __float2bfloat16_rn(v);
    l = __float2bfloat16_rn(v - __bfloat162float(h));
}

__device__ __forceinline__ void mma16(float* c, const uint32_t* a, uint32_t b0, uint32_t b1) {
    asm volatile("mma.sync.aligned.m16n8k16.row.col.f32.bf16.bf16.f32 "
                 "{%0,%1,%2,%3}, {%4,%5,%6,%7}, {%8,%9}, {%0,%1,%2,%3};"
                 : "+f"(c[0]), "+f"(c[1]), "+f"(c[2]), "+f"(c[3])
                 : "r"(a[0]), "r"(a[1]), "r"(a[2]), "r"(a[3]), "r"(b0), "r"(b1));
}

// ---------------- tf32 helpers (LM head only) ----------------
__device__ __forceinline__ void split2(float x, uint32_t& hi, uint32_t& lo) {
    uint32_t h;
    asm("cvt.rna.tf32.f32 %0, %1;" : "=r"(h) : "f"(x));
    float r = x - __uint_as_float(h);
    uint32_t l;
    asm("cvt.rna.tf32.f32 %0, %1;" : "=r"(l) : "f"(r));
    hi = h; lo = l;
}
__device__ __forceinline__ void mma8(float* c, const uint32_t* a, uint32_t b0, uint32_t b1) {
    asm volatile("mma.sync.aligned.m16n8k8.row.col.f32.tf32.tf32.f32 "
                 "{%0,%1,%2,%3}, {%4,%5,%6,%7}, {%8,%9}, {%0,%1,%2,%3};"
                 : "+f"(c[0]), "+f"(c[1]), "+f"(c[2]), "+f"(c[3])
                 : "r"(a[0]), "r"(a[1]), "r"(a[2]), "r"(a[3]), "r"(b0), "r"(b1));
}

// ---------------- misc helpers ----------------
__device__ __forceinline__ float blockReduceSum256(float v) {
    __shared__ float sh[8];
    int lane = threadIdx.x & 31;
    int wid  = threadIdx.x >> 5;
#pragma unroll
    for (int o = 16; o > 0; o >>= 1) v += __shfl_down_sync(0xffffffffu, v, o);
    __syncthreads();
    if (lane == 0) sh[wid] = v;
    __syncthreads();
    float t = 0.f;
#pragma unroll
    for (int i = 0; i < 8; i++) t += sh[i];
    return t;
}

// ---------------- embedding + positional ----------------
__global__ void embed_kernel(const int* __restrict__ ids,
                             const float* __restrict__ emb,
                             const float* __restrict__ pos,
                             float* __restrict__ X) {
    int row = blockIdx.x;
    int d   = threadIdx.x;
    int n   = row & (N_ - 1);
    int id  = ids[row];
    X[(size_t)row * D_ + d] = emb[(size_t)id * D_ + d] + pos[(size_t)n * D_ + d];
}

// ---------------- layernorm ----------------
__global__ void ln_kernel(const float* __restrict__ in,
                          const float* __restrict__ w,
                          const float* __restrict__ b,
                          const float* __restrict__ addX,
                          float* __restrict__ out,
                          float* __restrict__ out2) {
    int row = blockIdx.x;
    int d   = threadIdx.x;
    float x  = in[(size_t)row * D_ + d];
    float mu = blockReduceSum256(x) * (1.f / D_);
    float dx = x - mu;
    float var = blockReduceSum256(dx * dx) * (1.f / D_);
    float y = dx * rsqrtf(var + 1e-5f) * w[d] + b[d];
    if (addX) y += addX[(size_t)row * D_ + d];
    out[(size_t)row * D_ + d] = y;
    if (out2) out2[(size_t)row * D_ + d] = y;
}

// ============================================================================
// bf16x3 GEMM, 64x64x32 tiles, 256 threads (8 warps: 2m x 4n, warp tile 32x16)
// Supports up to 3 weight matrices (QKV fusion): block column group selects B.
// epi: 0 none, 1 elu(x)+1, 2 aux + softplus(dts[kidx])*x, 3 aux + x
// ============================================================================
#define GB3_SMEM ((4 * 64 * 17) * 4)

__global__ void __launch_bounds__(256)
gemm_b3(const float* __restrict__ A,
        const float* __restrict__ B0, const float* __restrict__ B1,
        const float* __restrict__ B2,
        float* __restrict__ C, int Kd, int N, int nblk, int ldc,
        int e0, int e1, int e2,
        const float* __restrict__ aux, const float* __restrict__ dts, int kidx)
{
    extern __shared__ uint32_t sh[];
    uint32_t* Ah = sh;                 // [64][17] packed bf16 pairs (k-major)
    uint32_t* Al = Ah + 64 * 17;
    uint32_t* Bh = Al + 64 * 17;       // [64 n][17] pairs along k
    uint32_t* Bl = Bh + 64 * 17;
    __nv_bfloat16* Bhb = (__nv_bfloat16*)Bh;
    __nv_bfloat16* Blb = (__nv_bfloat16*)Bl;

    const int tid  = threadIdx.x;
    const int lane = tid & 31;
    const int wid  = tid >> 5;
    const int g  = lane >> 2, tg = lane & 3;
    const int wm = wid & 1, wn = wid >> 1;     // 2 (m) x 4 (n)

    const int bx    = blockIdx.x;
    const int which = bx / nblk;
    const int bxl   = bx - which * nblk;
    const int col0  = bxl * 64;                  // within selected B
    const int ocol0 = which * N + col0;          // within C
    const int row0  = blockIdx.y * 64;
    const float* Bm = (which == 0) ? B0 : (which == 1) ? B1 : B2;
    const int epi   = (which == 0) ? e0 : (which == 1) ? e1 : e2;

    float acc[2][2][4];
#pragma unroll
    for (int a = 0; a < 2; a++)
#pragma unroll
        for (int b = 0; b < 2; b++)
#pragma unroll
            for (int c = 0; c < 4; c++) acc[a][b][c] = 0.f;

    for (int kt = 0; kt < Kd; kt += 32) {
        __syncthreads();
        // A tile 64x32 -> Ah/Al packed pairs (2 float4 per thread)
#pragma unroll
        for (int it = 0; it < 2; it++) {
            int flat = it * 256 + tid;
            int m  = flat >> 3;
            int kq = (flat & 7) << 2;
            float4 av = *(const float4*)(A + (size_t)(row0 + m) * Kd + kt + kq);
            __nv_bfloat16 h0, l0, h1, l1, h2, l2, h3, l3;
            split_bf(av.x, h0, l0); split_bf(av.y, h1, l1);
            split_bf(av.z, h2, l2); split_bf(av.w, h3, l3);
            int base = m * 17 + (kq >> 1);
            Ah[base]     = pack_bf2(__bfloat162float(h0), __bfloat162float(h1));
            Ah[base + 1] = pack_bf2(__bfloat162float(h2), __bfloat162float(h3));
            Al[base]     = pack_bf2(__bfloat162float(l0), __bfloat162float(l1));
            Al[base + 1] = pack_bf2(__bfloat162float(l2), __bfloat162float(l3));
        }
        // B tile 32k x 64n -> transposed [n][k] bf16 (2 float4 per thread)
#pragma unroll
        for (int it = 0; it < 2; it++) {
            int flat = it * 256 + tid;
            int kk = flat >> 4;               // k row 0..31
            int nq = (flat & 15) << 2;        // n col
            float4 bv = *(const float4*)(Bm + (size_t)(kt + kk) * N + col0 + nq);
            float vv[4] = {bv.x, bv.y, bv.z, bv.w};
#pragma unroll
            for (int j = 0; j < 4; j++) {
                __nv_bfloat16 h, l; split_bf(vv[j], h, l);
                Bhb[(nq + j) * 34 + kk] = h;
                Blb[(nq + j) * 34 + kk] = l;
            }
        }
        __syncthreads();

#pragma unroll
        for (int ks = 0; ks < 2; ks++) {        // two k16 slices
            int kb = ks * 8;
            uint32_t ah[2][4], al[2][4];
#pragma unroll
            for (int mt = 0; mt < 2; mt++) {
                int r = wm * 32 + mt * 16;
                ah[mt][0] = Ah[(r + g) * 17 + kb + tg];
                ah[mt][1] = Ah[(r + g + 8) * 17 + kb + tg];
                ah[mt][2] = Ah[(r + g) * 17 + kb + tg + 4];
                ah[mt][3] = Ah[(r + g + 8) * 17 + kb + tg + 4];
                al[mt][0] = Al[(r + g) * 17 + kb + tg];
                al[mt][1] = Al[(r + g + 8) * 17 + kb + tg];
                al[mt][2] = Al[(r + g) * 17 + kb + tg + 4];
                al[mt][3] = Al[(r + g + 8) * 17 + kb + tg + 4];
            }
#pragma unroll
            for (int nt = 0; nt < 2; nt++) {
                int c = wn * 16 + nt * 8;
                uint32_t bh0 = Bh[(c + g) * 17 + kb + tg];
                uint32_t bh1 = Bh[(c + g) * 17 + kb + tg + 4];
                uint32_t bl0 = Bl[(c + g) * 17 + kb + tg];
                uint32_t bl1 = Bl[(c + g) * 17 + kb + tg + 4];
#pragma unroll
                for (int mt = 0; mt < 2; mt++) {
                    mma16(acc[mt][nt], ah[mt], bh0, bh1);
                    mma16(acc[mt][nt], al[mt], bh0, bh1);
                    mma16(acc[mt][nt], ah[mt], bl0, bl1);
                }
            }
        }
    }

    float sp = (epi == 2) ? log1pf(expf(dts[kidx])) : 0.f;
#pragma unroll
    for (int mt = 0; mt < 2; mt++) {
#pragma unroll
        for (int nt = 0; nt < 2; nt++) {
            int r = row0 + wm * 32 + mt * 16 + g;
            int c = ocol0 + wn * 16 + nt * 8 + 2 * tg;
#pragma unroll
            for (int e = 0; e < 4; e++) {
                int rr = r + (e >> 1) * 8;
                int cc = c + (e & 1);
                size_t o = (size_t)rr * ldc + cc;
                float x = acc[mt][nt][e];
                float y;
                if (epi == 1)      y = (x > 0.f) ? (x + 1.f) : expf(x);
                else if (epi == 2) y = aux[o] + sp * x;
                else if (epi == 3) y = aux[o] + x;
                else               y = x;
                C[o] = y;
            }
        }
    }
}

// ============================================================================
// bf16x3 attention: per (b,h,q64): S = pq@pk^T, W = relu(S)^2, C = W@v,
// out = C/(rowsum+1) - v.  pq/pk/v strided (QKVS) from fused buffer.
// ============================================================================
#define ATT_SMEM ((4 * 64 * 17 + 2 * 32 * 33 + 64 * 68 + 256 + 64) * 4)

__global__ void __launch_bounds__(256)
attn_tc(const float* __restrict__ pq_, const float* __restrict__ pk_,
        const float* __restrict__ v_, float* __restrict__ cmv)
{
    extern __shared__ uint32_t sh[];
    uint32_t* qh = sh;                  // [64][17] pairs along dh
    uint32_t* ql = qh + 64 * 17;
    uint32_t* kh = ql + 64 * 17;        // [64 tok][17] pairs along dh
    uint32_t* kl = kh + 64 * 17;
    uint32_t* vh = kl + 64 * 17;        // [32 dh][33] pairs along token
    uint32_t* vl = vh + 32 * 33;
    float* Ssm  = (float*)(vl + 32 * 33);  // 64 x 68
    float* ssum = Ssm + 64 * 68;           // 256
    float* sinv = ssum + 256;              // 64
    __nv_bfloat16* vhb = (__nv_bfloat16*)vh;
    __nv_bfloat16* vlb = (__nv_bfloat16*)vl;

    const int tid  = threadIdx.x;
    const int lane = tid & 31, wid = tid >> 5;
    const int g = lane >> 2, tg = lane & 3;
    const int wm = wid & 1, wn = wid >> 1;   // 2 (m) x 4 (n)
    const int bh = blockIdx.x;
    const int b = bh >> 3, h = bh & 7;
    const int qb = blockIdx.y;

    // load pq tile (64 x 32), split+pack
#pragma unroll
    for (int it = 0; it < 2; it++) {
        int flat = it * 256 + tid;
        int r  = flat >> 3;
        int dq = (flat & 7) << 2;
        float4 av = *(const float4*)(pq_ + (size_t)(b * N_ + qb * 64 + r) * QKVS + h * DH_ + dq);
        __nv_bfloat16 h0, l0, h1, l1, h2, l2, h3, l3;
        split_bf(av.x, h0, l0); split_bf(av.y, h1, l1);
        split_bf(av.z, h2, l2); split_bf(av.w, h3, l3);
        int base = r * 17 + (dq >> 1);
        qh[base]     = pack_bf2(__bfloat162float(h0), __bfloat162float(h1));
        qh[base + 1] = pack_bf2(__bfloat162float(h2), __bfloat162float(h3));
        ql[base]     = pack_bf2(__bfloat162float(l0), __bfloat162float(l1));
        ql[base + 1] = pack_bf2(__bfloat162float(l2), __bfloat162float(l3));
    }

    float cacc[2][4];
#pragma unroll
    for (int mt = 0; mt < 2; mt++)
#pragma unroll
        for (int e = 0; e < 4; e++) cacc[mt][e] = 0.f;
    float srow = 0.f;
    const int myrow = tid >> 2, myq = tid & 3;

    for (int kt = 0; kt < N_; kt += 64) {
        __syncthreads();
        // load pk (pairs along dh) and v (transposed: pairs along token)
#pragma unroll
        for (int it = 0; it < 2; it++) {
            int flat = it * 256 + tid;
            int r  = flat >> 3;
            int dq = (flat & 7) << 2;
            size_t go = (size_t)(b * N_ + kt + r) * QKVS + h * DH_ + dq;
            float4 kv4 = *(const float4*)(pk_ + go);
            float4 vv4 = *(const float4*)(v_ + go);
            {
                __nv_bfloat16 h0, l0, h1, l1, h2, l2, h3, l3;
                split_bf(kv4.x, h0, l0); split_bf(kv4.y, h1, l1);
                split_bf(kv4.z, h2, l2); split_bf(kv4.w, h3, l3);
                int base = r * 17 + (dq >> 1);
                kh[base]     = pack_bf2(__bfloat162float(h0), __bfloat162float(h1));
                kh[base + 1] = pack_bf2(__bfloat162float(h2), __bfloat162float(h3));
                kl[base]     = pack_bf2(__bfloat162float(l0), __bfloat162float(l1));
                kl[base + 1] = pack_bf2(__bfloat162float(l2), __bfloat162float(l3));
            }
            {
                float vv[4] = {vv4.x, vv4.y, vv4.z, vv4.w};
#pragma unroll
                for (int j = 0; j < 4; j++) {
                    __nv_bfloat16 hh, ll; split_bf(vv[j], hh, ll);
                    vhb[(dq + j) * 66 + r] = hh;
                    vlb[(dq + j) * 66 + r] = ll;
                }
            }
        }
        __syncthreads();

        // phase 1: S = pq @ pk^T, warp tile 32x16
        float sacc[2][2][4];
#pragma unroll
        for (int mt = 0; mt < 2; mt++)
#pragma unroll
            for (int nt = 0; nt < 2; nt++)
#pragma unroll
                for (int e = 0; e < 4; e++) sacc[mt][nt][e] = 0.f;

#pragma unroll
        for (int ks = 0; ks < 2; ks++) {        // dh = 32 -> two k16 slices
            int kb = ks * 8;
            uint32_t ah[2][4], al[2][4];
#pragma unroll
            for (int mt = 0; mt < 2; mt++) {
                int r = wm * 32 + mt * 16;
                ah[mt][0] = qh[(r + g) * 17 + kb + tg];
                ah[mt][1] = qh[(r + g + 8) * 17 + kb + tg];
                ah[mt][2] = qh[(r + g) * 17 + kb + tg + 4];
                ah[mt][3] = qh[(r + g + 8) * 17 + kb + tg + 4];
                al[mt][0] = ql[(r + g) * 17 + kb + tg];
                al[mt][1] = ql[(r + g + 8) * 17 + kb + tg];
                al[mt][2] = ql[(r + g) * 17 + kb + tg + 4];
                al[mt][3] = ql[(r + g + 8) * 17 + kb + tg + 4];
            }
#pragma unroll
            for (int nt = 0; nt < 2; nt++) {
                int c = wn * 16 + nt * 8;
                uint32_t bh0 = kh[(c + g) * 17 + kb + tg];
                uint32_t bh1 = kh[(c + g) * 17 + kb + tg + 4];
                uint32_t bl0 = kl[(c + g) * 17 + kb + tg];
                uint32_t bl1 = kl[(c + g) * 17 + kb + tg + 4];
#pragma unroll
                for (int mt = 0; mt < 2; mt++) {
                    mma16(sacc[mt][nt], ah[mt], bh0, bh1);
                    mma16(sacc[mt][nt], al[mt], bh0, bh1);
                    mma16(sacc[mt][nt], ah[mt], bl0, bl1);
                }
            }
        }
        // relu^2 -> Ssm
#pragma unroll
        for (int mt = 0; mt < 2; mt++)
#pragma unroll
            for (int nt = 0; nt < 2; nt++) {
                int r = wm * 32 + mt * 16 + g;
                int c = wn * 16 + nt * 8 + 2 * tg;
#pragma unroll
                for (int e = 0; e < 4; e++) {
                    int rr = r + (e >> 1) * 8, cc = c + (e & 1);
                    float w = fmaxf(sacc[mt][nt][e], 0.f);
                    Ssm[rr * 68 + cc] = w * w;
                }
            }
        __syncthreads();

        // rowsum partial
        {
            const float* spp = Ssm + myrow * 68 + myq * 16;
            float t = 0.f;
#pragma unroll
            for (int j = 0; j < 16; j++) t += spp[j];
            srow += t;
        }

        // phase 2: C += P @ v, warp tile 32 rows x 8 dh cols
#pragma unroll
        for (int ks = 0; ks < 4; ks++) {       // token = 64 -> four k16 slices
            int kb = ks * 16;
            uint32_t ah2[2][4], al2[2][4];
#pragma unroll
            for (int mt = 0; mt < 2; mt++) {
                int r = wm * 32 + mt * 16;
                const float* S0 = Ssm + (r + g) * 68 + kb;
                const float* S1 = Ssm + (r + g + 8) * 68 + kb;
                float f0a = S0[2 * tg],     f0b = S0[2 * tg + 1];
                float f1a = S1[2 * tg],     f1b = S1[2 * tg + 1];
                float f2a = S0[2 * tg + 8], f2b = S0[2 * tg + 9];
                float f3a = S1[2 * tg + 8], f3b = S1[2 * tg + 9];
                __nv_bfloat16 hh, ll;
                float h0a, l0a, h0b, l0b;
                split_bf(f0a, hh, ll); h0a = __bfloat162float(hh); l0a = __bfloat162float(ll);
                split_bf(f0b, hh, ll); h0b = __bfloat162float(hh); l0b = __bfloat162float(ll);
                ah2[mt][0] = pack_bf2(h0a, h0b); al2[mt][0] = pack_bf2(l0a, l0b);
                split_bf(f1a, hh, ll); h0a = __bfloat162float(hh); l0a = __bfloat162float(ll);
                split_bf(f1b, hh, ll); h0b = __bfloat162float(hh); l0b = __bfloat162float(ll);
                ah2[mt][1] = pack_bf2(h0a, h0b); al2[mt][1] = pack_bf2(l0a, l0b);
                split_bf(f2a, hh, ll); h0a = __bfloat162float(hh); l0a = __bfloat162float(ll);
                split_bf(f2b, hh, ll); h0b = __bfloat162float(hh); l0b = __bfloat162float(ll);
                ah2[mt][2] = pack_bf2(h0a, h0b); al2[mt][2] = pack_bf2(l0a, l0b);
                split_bf(f3a, hh, ll); h0a = __bfloat162float(hh); l0a = __bfloat162float(ll);
                split_bf(f3b, hh, ll); h0b = __bfloat162float(hh); l0b = __bfloat162float(ll);
                ah2[mt][3] = pack_bf2(h0a, h0b); al2[mt][3] = pack_bf2(l0a, l0b);
            }
            int c = wn * 8;
            uint32_t bh0 = vh[(c + g) * 33 + ks * 8 + tg];
            uint32_t bh1 = vh[(c + g) * 33 + ks * 8 + tg + 4];
            uint32_t bl0 = vl[(c + g) * 33 + ks * 8 + tg];
            uint32_t bl1 = vl[(c + g) * 33 + ks * 8 + tg + 4];
#pragma unroll
            for (int mt = 0; mt < 2; mt++) {
                mma16(cacc[mt], ah2[mt], bh0, bh1);
                mma16(cacc[mt], al2[mt], bh0, bh1);
                mma16(cacc[mt], ah2[mt], bl0, bl1);
            }
        }
    }

    // rowsum reduce
    ssum[myrow * 4 + myq] = srow;
    __syncthreads();
    if (tid < 64) {
        float s = ssum[tid * 4] + ssum[tid * 4 + 1] + ssum[tid * 4 + 2] + ssum[tid * 4 + 3];
        sinv[tid] = 1.f / (s + 1.f);
    }
    __syncthreads();

    // epilogue: out = C * inv - v
#pragma unroll
    for (int mt = 0; mt < 2; mt++) {
        int rl = wm * 32 + mt * 16 + g;
        int cl = wn * 8 + 2 * tg;
#pragma unroll
        for (int e = 0; e < 4; e++) {
            int rr = rl + (e >> 1) * 8;
            int cc = cl + (e & 1);
            size_t vo = (size_t)(b * N_ + qb * 64 + rr) * QKVS + h * DH_ + cc;
            size_t oo = (size_t)(b * N_ + qb * 64 + rr) * D_ + h * DH_ + cc;
            cmv[oo] = cacc[mt][e] * sinv[rr] - v_[vo];
        }
    }
}

// ============================================================================
// tf32 x1 GEMM (LM head only): 128x64x32 tiles
// ============================================================================
#define GEMM_SMEM_1 (((128 * 33) + (32 * 65)) * 4)

__global__ void __launch_bounds__(256, 2)
gemm_lm(const float* __restrict__ A, const float* __restrict__ Bm, float* __restrict__ C,
        int N, int Kd)
{
    extern __shared__ uint32_t sh[];
    uint32_t* Ah = sh;                      // 128*33
    uint32_t* Bh = Ah + 128 * 33;           // 32*65

    const int tid  = threadIdx.x;
    const int lane = tid & 31;
    const int wid  = tid >> 5;
    const int g  = lane >> 2, tg = lane & 3;
    const int wm = wid & 3,   wn = wid >> 2;          // 4 (m) x 2 (n)
    const int row0 = blockIdx.y * 128;
    const int col0 = blockIdx.x * 64;

    float acc[2][4][4];
#pragma unroll
    for (int a = 0; a < 2; a++)
#pragma unroll
        for (int b = 0; b < 4; b++)
#pragma unroll
            for (int c = 0; c < 4; c++) acc[a][b][c] = 0.f;

    for (int kt = 0; kt < Kd; kt += 32) {
        __syncthreads();
#pragma unroll
        for (int it = 0; it < 4; it++) {
            int flat = it * 256 + tid;
            int m  = flat >> 3;
            int kq = (flat & 7) << 2;
            float4 av = *(const float4*)(A + (size_t)(row0 + m) * Kd + kt + kq);
            float vv[4] = {av.x, av.y, av.z, av.w};
#pragma unroll
            for (int j = 0; j < 4; j++) {
                uint32_t hi, lo; split2(vv[j], hi, lo);
                Ah[m * 33 + kq + j] = hi;
            }
        }
#pragma unroll
        for (int it = 0; it < 2; it++) {
            int flat = it * 256 + tid;
            int kk = flat >> 4;
            int nq = (flat & 15) << 2;
            float4 bv = *(const float4*)(Bm + (size_t)(kt + kk) * N + col0 + nq);
            float vv[4] = {bv.x, bv.y, bv.z, bv.w};
#pragma unroll
            for (int j = 0; j < 4; j++) {
                uint32_t hi, lo; split2(vv[j], hi, lo);
                Bh[kk * 65 + nq + j] = hi;
            }
        }
        __syncthreads();

#pragma unroll
        for (int ks = 0; ks < 4; ks++) {
            int kb = ks * 8;
            uint32_t ah[2][4];
#pragma unroll
            for (int mt = 0; mt < 2; mt++) {
                int r = wm * 32 + mt * 16;
                ah[mt][0] = Ah[(r + g) * 33 + kb + tg];
                ah[mt][1] = Ah[(r + g + 8) * 33 + kb + tg];
                ah[mt][2] = Ah[(r + g) * 33 + kb + tg + 4];
                ah[mt][3] = Ah[(r + g + 8) * 33 + kb + tg + 4];
            }
#pragma unroll
            for (int nt = 0; nt < 4; nt++) {
                int c = wn * 32 + nt * 8;
                uint32_t bh0 = Bh[(kb + tg) * 65 + c + g];
                uint32_t bh1 = Bh[(kb + tg + 4) * 65 + c + g];
#pragma unroll
                for (int mt = 0; mt < 2; mt++) mma8(acc[mt][nt], ah[mt], bh0, bh1);
            }
        }
    }

#pragma unroll
    for (int mt = 0; mt < 2; mt++) {
#pragma unroll
        for (int nt = 0; nt < 4; nt++) {
            int r = row0 + wm * 32 + mt * 16 + g;
            int c = col0 + wn * 32 + nt * 8 + 2 * tg;
#pragma unroll
            for (int e = 0; e < 4; e++) {
                int rr = r + (e >> 1) * 8;
                int cc = c + (e & 1);
                C[(size_t)rr * N + cc] = acc[mt][nt][e];
            }
        }
    }
}

// ---------------- fused silu-gate + depthwise conv3 ----------------
__global__ void siluconv_kernel(const float* __restrict__ gu, const float* __restrict__ cw,
                                int kidx, float* __restrict__ out) {
    int idx = blockIdx.x * 256 + threadIdx.x;
    int i   = idx & (IN_ - 1);
    int bn  = idx >> 10;
    int n   = bn & (N_ - 1);
    const float* wp = cw + ((size_t)kidx * IN_ + i) * CK_;

    float gC = gu[(size_t)bn * (2 * IN_) + i];
    float uC = gu[(size_t)bn * (2 * IN_) + IN_ + i];
    float a = wp[1] * (gC / (1.f + expf(-gC)) * uC);
    if (n > 0) {
        float gm = gu[(size_t)(bn - 1) * (2 * IN_) + i];
        float um = gu[(size_t)(bn - 1) * (2 * IN_) + IN_ + i];
        a = fmaf(wp[0], gm / (1.f + expf(-gm)) * um, a);
    }
    if (n < N_ - 1) {
        float gp = gu[(size_t)(bn + 1) * (2 * IN_) + i];
        float up = gu[(size_t)(bn + 1) * (2 * IN_) + IN_ + i];
        a = fmaf(wp[2], gp / (1.f + expf(-gp)) * up, a);
    }
    out[idx] = a;
}

// ---------------- halt head ----------------
__global__ void halt_kernel(const float* __restrict__ qn, const float* __restrict__ hw,
                            const float* __restrict__ hb, float* __restrict__ out, int l4) {
    int b = blockIdx.x;
    int d = threadIdx.x;
    float s = 0.f;
    for (int n = 0; n < N_; n++) s += qn[(size_t)(b * N_ + n) * D_ + d];
    float p = (s * (1.f / N_)) * hw[d];
    float tot = blockReduceSum256(p);
    if (threadIdx.x == 0)
        out[l4 * B_ + b] = 1.f / (1.f + expf(-(tot + hb[0])));
}

// ---------------- host orchestration ----------------
static inline float* symaddr(const void* sym) {
    void* p = nullptr;
    cudaGetSymbolAddress(&p, sym);
    return (float*)p;
}

extern "C" void kernel_launch(void* const* d_in, const int* in_sizes, int n_in,
                              void* d_out, int out_size) {
    const int*   ids   = (const int*)  d_in[0];
    const float* emb   = (const float*)d_in[1];
    const float* pos   = (const float*)d_in[2];
    const float* in_w  = (const float*)d_in[3];
    const float* in_b  = (const float*)d_in[4];
    const float* Wq    = (const float*)d_in[5];
    const float* Wk    = (const float*)d_in[6];
    const float* Wv    = (const float*)d_in[7];
    const float* Wo    = (const float*)d_in[8];
    const float* dts   = (const float*)d_in[9];
    const float* Wup   = (const float*)d_in[10];
    const float* cw    = (const float*)d_in[11];
    const float* Wd    = (const float*)d_in[12];
    const float* n1w   = (const float*)d_in[13];
    const float* n1b   = (const float*)d_in[14];
    const float* n2w   = (const float*)d_in[15];
    const float* n2b   = (const float*)d_in[16];
    const float* fin_w = (const float*)d_in[17];
    const float* fin_b = (const float*)d_in[18];
    const float* haltw = (const float*)d_in[19];
    const float* haltb = (const float*)d_in[20];
    const float* lm_w  = (const float*)d_in[21];

    float* out        = (float*)d_out;
    float* out_logits = out;
    float* out_halts  = out + (size_t)out_size - (size_t)(MAXL_ - TRUNC_) * B_;

    float* pX   = symaddr(g_X);
    float* pQ   = symaddr(g_Q);
    float* pHc  = symaddr(g_Hc);
    float* pQKV = symaddr(g_qkv);
    float* pCmv = symaddr(g_cmv);
    float* pHn  = symaddr(g_hn);
    float* pGU  = symaddr(g_gu);
    float* pHc2 = symaddr(g_hc2);
    float* pQn  = symaddr(g_qn);

    cudaFuncSetAttribute(gemm_b3, cudaFuncAttributeMaxDynamicSharedMemorySize, GB3_SMEM);
    cudaFuncSetAttribute(attn_tc, cudaFuncAttributeMaxDynamicSharedMemorySize, ATT_SMEM);
    cudaFuncSetAttribute(gemm_lm, cudaFuncAttributeMaxDynamicSharedMemorySize, GEMM_SMEM_1);

    // X = ln(emb[ids] + pos);  Q = X
    embed_kernel<<<BN_, 256>>>(ids, emb, pos, pX);
    ln_kernel<<<BN_, 256>>>(pX, in_w, in_b, nullptr, pX, pQ);

    const dim3 gQKV(12, BN_ / 64);      // 3 matrices x 4 col blocks, 32 row blocks
    const dim3 gDD(4, BN_ / 64);        // N=256
    const dim3 gUP(32, BN_ / 64);       // N=2048
    const dim3 gLM(V_ / 64, BN_ / 128); // (500, 16)
    const int  ec = (BN_ * IN_) / 256;

    for (int l = 0; l < MAXL_; l++) {
        for (int k = 0; k < K_; k++) {
            // Hc = ln(Q; n1) + X
            ln_kernel<<<BN_, 256>>>(pQ, n1w + k * D_, n1b + k * D_, pX, pHc, nullptr);
            // fused qkv: [pq | pk | v] = [elu+1(Hc@Wq) | elu+1(Hc@Wk) | Hc@Wv]
            gemm_b3<<<gQKV, 256, GB3_SMEM>>>(pHc,
                                             Wq + (size_t)k * D_ * D_,
                                             Wk + (size_t)k * D_ * D_,
                                             Wv + (size_t)k * D_ * D_,
                                             pQKV, D_, D_, 4, QKVS,
                                             1, 1, 0, nullptr, nullptr, 0);
            // cmv = (relu(pq pk^T)^2 @ v) / (rowsum + 1) - v
            attn_tc<<<dim3(B_ * H_, N_ / 64), 256, ATT_SMEM>>>(pQKV, pQKV + D_,
                                                               pQKV + 2 * D_, pCmv);
            // Q = Q + softplus(dt_k) * (cmv @ Wo)
            gemm_b3<<<gDD, 256, GB3_SMEM>>>(pCmv, Wo + (size_t)k * D_ * D_,
                                            nullptr, nullptr, pQ, D_, D_, 4, D_,
                                            2, 2, 2, pQ, dts, k);
            // Hn = ln(Q; n2); GU = Hn @ Wup
            ln_kernel<<<BN_, 256>>>(pQ, n2w + k * D_, n2b + k * D_, nullptr, pHn, nullptr);
            gemm_b3<<<gUP, 256, GB3_SMEM>>>(pHn, Wup + (size_t)k * D_ * 2 * IN_,
                                            nullptr, nullptr, pGU, D_, 2 * IN_, 32, 2 * IN_,
                                            0, 0, 0, nullptr, nullptr, 0);
            // Hc2 = conv3(silu(G)*U); Q = Q + Hc2 @ Wd
            siluconv_kernel<<<ec, 256>>>(pGU, cw, k, pHc2);
            gemm_b3<<<gDD, 256, GB3_SMEM>>>(pHc2, Wd + (size_t)k * IN_ * D_,
                                            nullptr, nullptr, pQ, IN_, D_, 4, D_,
                                            3, 3, 3, pQ, nullptr, 0);
        }
        if (l >= TRUNC_) {
            int l4 = l - TRUNC_;
            ln_kernel<<<BN_, 256>>>(pQ, fin_w, fin_b, nullptr, pQn, nullptr);
            halt_kernel<<<B_, 256>>>(pQn, haltw, haltb, out_halts, l4);
            gemm_lm<<<gLM, 256, GEMM_SMEM_1>>>(pQn, lm_w,
                                               out_logits + (size_t)l4 * BN_ * V_,
                                               V_, D_);
        }
    }
}